// round 3
// baseline (speedup 1.0000x reference)
#include <cuda_runtime.h>
#include <cuda_bf16.h>
#include <cstdint>

#define BATCH 32
#define NN    1024
#define NDIM  14
#define HID   64
#define HEAD  128
#define MAXD  64
#define TOTAL_NODES (BATCH * NN)   // 32768

// ---------------- device scratch ----------------
__device__ int   g_nbr[TOTAL_NODES * MAXD];
__device__ int   g_cnt[TOTAL_NODES];
__device__ float g_dinv[TOTAL_NODES];
__device__ float g_h1[TOTAL_NODES * HID];
__device__ float g_h2[TOTAL_NODES * HID];
__device__ float g_pool[(TOTAL_NODES / 64) * HID];   // one partial per 64-node block

// ---------------- 1) adjacency scan (float4, warp per row) ----------------
__global__ void build_edges_kernel(const float* __restrict__ adj) {
    int row  = blockIdx.x * 8 + (threadIdx.x >> 5);
    int lane = threadIdx.x & 31;
    if (row >= TOTAL_NODES) return;

    const float4* arow = (const float4*)(adj + (size_t)row * NN);
    int* nl = &g_nbr[(size_t)row * MAXD];
    int cnt = 0;
    const unsigned lt = (1u << lane) - 1u;

    #pragma unroll
    for (int s = 0; s < NN / 128; s++) {           // 8 iterations
        float4 v = arow[s * 32 + lane];
        bool b0 = v.x > 0.5f, b1 = v.y > 0.5f, b2 = v.z > 0.5f, b3 = v.w > 0.5f;
        unsigned m0 = __ballot_sync(0xffffffffu, b0);
        unsigned m1 = __ballot_sync(0xffffffffu, b1);
        unsigned m2 = __ballot_sync(0xffffffffu, b2);
        unsigned m3 = __ballot_sync(0xffffffffu, b3);
        int prior = __popc(m0 & lt) + __popc(m1 & lt) + __popc(m2 & lt) + __popc(m3 & lt);
        int colbase = s * 128 + lane * 4;
        int p = cnt + prior;
        if (b0) { if (p < MAXD) nl[p] = colbase + 0; p++; }
        if (b1) { if (p < MAXD) nl[p] = colbase + 1; p++; }
        if (b2) { if (p < MAXD) nl[p] = colbase + 2; p++; }
        if (b3) { if (p < MAXD) nl[p] = colbase + 3; }
        cnt += __popc(m0) + __popc(m1) + __popc(m2) + __popc(m3);
    }
    if (lane == 0) {
        g_cnt[row]  = cnt < MAXD ? cnt : MAXD;
        g_dinv[row] = rsqrtf((float)cnt);
    }
}

// ---------------- 2) fused sparse-gather + GEMM + bias + ReLU ----------------
// SCALE_IN : multiply gathered rows by dinv_j (layer 1 only; later layers read
//            pre-scaled activations).
// SCALE_OUT: write dinv_i * relu(...) (layers 1,2).
// POOL     : accumulate block-level column sums of the (unscaled) outputs into
//            g_pool[blockIdx.x] (layer 3).
template <int DIN, bool SCALE_IN, bool SCALE_OUT, bool POOL>
__global__ __launch_bounds__(256)
void gcn_layer_kernel(const float* __restrict__ in,
                      const float* __restrict__ W,
                      const float* __restrict__ bias,
                      float* __restrict__ out) {
    constexpr int KPAD = (DIN + 3) & ~3;
    __shared__ float Ag[64][68];          // gathered tile (node-major)
    __shared__ float Ws[KPAD][64];
    __shared__ float bs[64];

    const int tid       = threadIdx.x;
    const int blockBase = blockIdx.x * 64;
    const int bbase     = blockBase & ~(NN - 1);

    for (int i = tid; i < KPAD * 64; i += 256) {
        int r = i >> 6;
        Ws[r][i & 63] = (r < DIN) ? W[r * 64 + (i & 63)] : 0.0f;
    }
    if (tid < 64) bs[tid] = bias[tid];

    // ---- Phase A: gather, 16 threads per 4-node group, nodes interleaved ----
    {
        const int grp  = tid >> 4;   // 0..15
        const int lane = tid & 15;   // 0..15
        const int nodeBase = blockBase + grp * 4;

        int cnt4[4];
        const int* nl4[4];
        #pragma unroll
        for (int s = 0; s < 4; s++) {
            cnt4[s] = g_cnt[nodeBase + s];
            nl4[s]  = &g_nbr[(size_t)(nodeBase + s) * MAXD];
        }
        int cmax = max(max(cnt4[0], cnt4[1]), max(cnt4[2], cnt4[3]));

        if (DIN == 64) {
            float4 acc4[4];
            #pragma unroll
            for (int s = 0; s < 4; s++) acc4[s] = make_float4(0.f, 0.f, 0.f, 0.f);

            #pragma unroll 2
            for (int j = 0; j < cmax; j++) {
                #pragma unroll
                for (int s = 0; s < 4; s++) {
                    if (j < cnt4[s]) {
                        const int jj = nl4[s][j];
                        const float4 v = *(const float4*)(in + (size_t)(bbase + jj) * 64 + lane * 4);
                        const float d = SCALE_IN ? g_dinv[bbase + jj] : 1.0f;
                        acc4[s].x += d * v.x; acc4[s].y += d * v.y;
                        acc4[s].z += d * v.z; acc4[s].w += d * v.w;
                    }
                }
            }
            #pragma unroll
            for (int s = 0; s < 4; s++) {
                const float di = g_dinv[nodeBase + s];
                float4 a = acc4[s];
                a.x *= di; a.y *= di; a.z *= di; a.w *= di;
                *(float4*)&Ag[grp * 4 + s][lane * 4] = a;
            }
        } else {
            // DIN = 14: lanes 0..13 each own one k; lanes 14,15 pad zeros
            float acc4[4] = {0.f, 0.f, 0.f, 0.f};
            if (lane < DIN) {
                #pragma unroll 2
                for (int j = 0; j < cmax; j++) {
                    #pragma unroll
                    for (int s = 0; s < 4; s++) {
                        if (j < cnt4[s]) {
                            const int jj = nl4[s][j];
                            const float v = in[(size_t)(bbase + jj) * DIN + lane];
                            const float d = SCALE_IN ? g_dinv[bbase + jj] : 1.0f;
                            acc4[s] += d * v;
                        }
                    }
                }
                #pragma unroll
                for (int s = 0; s < 4; s++)
                    Ag[grp * 4 + s][lane] = g_dinv[nodeBase + s] * acc4[s];
            } else if (lane < KPAD) {
                #pragma unroll
                for (int s = 0; s < 4; s++) Ag[grp * 4 + s][lane] = 0.0f;
            }
        }
    }
    __syncthreads();

    // ---- Phase B: [64 x KPAD] @ [KPAD x 64], 4x4 microtiles ----
    {
        const int tx = tid & 15;
        const int ty = tid >> 4;
        float c[4][4];
        #pragma unroll
        for (int i = 0; i < 4; i++)
            #pragma unroll
            for (int j = 0; j < 4; j++) c[i][j] = 0.0f;

        #pragma unroll
        for (int kk = 0; kk < KPAD; kk += 4) {
            float4 a[4], b[4];
            #pragma unroll
            for (int i = 0; i < 4; i++) a[i] = *(const float4*)&Ag[ty * 4 + i][kk];
            #pragma unroll
            for (int q = 0; q < 4; q++) b[q] = *(const float4*)&Ws[kk + q][tx * 4];
            #pragma unroll
            for (int i = 0; i < 4; i++) {
                const float ai[4] = {a[i].x, a[i].y, a[i].z, a[i].w};
                #pragma unroll
                for (int q = 0; q < 4; q++) {
                    c[i][0] = fmaf(ai[q], b[q].x, c[i][0]);
                    c[i][1] = fmaf(ai[q], b[q].y, c[i][1]);
                    c[i][2] = fmaf(ai[q], b[q].z, c[i][2]);
                    c[i][3] = fmaf(ai[q], b[q].w, c[i][3]);
                }
            }
        }

        float colsum[4] = {0.f, 0.f, 0.f, 0.f};
        #pragma unroll
        for (int i = 0; i < 4; i++) {
            const int row = blockBase + ty * 4 + i;
            const float dscale = SCALE_OUT ? g_dinv[row] : 1.0f;
            float4 o;
            o.x = fmaxf(c[i][0] + bs[tx * 4 + 0], 0.0f);
            o.y = fmaxf(c[i][1] + bs[tx * 4 + 1], 0.0f);
            o.z = fmaxf(c[i][2] + bs[tx * 4 + 2], 0.0f);
            o.w = fmaxf(c[i][3] + bs[tx * 4 + 3], 0.0f);
            if (POOL) {
                colsum[0] += o.x; colsum[1] += o.y;
                colsum[2] += o.z; colsum[3] += o.w;
            }
            o.x *= dscale; o.y *= dscale; o.z *= dscale; o.w *= dscale;
            *(float4*)&out[(size_t)row * 64 + tx * 4] = o;
        }

        if (POOL) {
            __syncthreads();               // done reading Ag; reuse it
            #pragma unroll
            for (int q = 0; q < 4; q++) Ag[ty][tx * 4 + q] = colsum[q];
            __syncthreads();
            if (tid < 64) {
                float s = 0.0f;
                #pragma unroll
                for (int r = 0; r < 16; r++) s += Ag[r][tid];
                g_pool[blockIdx.x * HID + tid] = s;
            }
        }
    }
}

// ---------------- 3) head: combine partials + MLP ----------------
__global__ void head_kernel(const float* __restrict__ Wf1,
                            const float* __restrict__ bf1,
                            const float* __restrict__ Wf2,
                            const float* __restrict__ bf2,
                            float* __restrict__ out) {
    const int b = blockIdx.x, tid = threadIdx.x;
    __shared__ float pooled[64];
    __shared__ float red[128];

    if (tid < 64) {
        float s = 0.0f;
        #pragma unroll
        for (int c = 0; c < 16; c++) s += g_pool[(b * 16 + c) * HID + tid];
        pooled[tid] = s * (1.0f / (float)NN);
    }
    __syncthreads();

    float a = bf1[tid];
    #pragma unroll
    for (int kk = 0; kk < 64; kk++) a = fmaf(pooled[kk], Wf1[kk * HEAD + tid], a);
    red[tid] = fmaxf(a, 0.0f) * Wf2[tid];
    __syncthreads();
    for (int off = 64; off > 0; off >>= 1) {
        if (tid < off) red[tid] += red[tid + off];
        __syncthreads();
    }
    if (tid == 0) out[b] = red[0] + bf2[0];
}

// ---------------- launch ----------------
extern "C" void kernel_launch(void* const* d_in, const int* in_sizes, int n_in,
                              void* d_out, int out_size) {
    const float* x   = (const float*)d_in[0];
    const float* adj = (const float*)d_in[1];
    const float* W1  = (const float*)d_in[2];
    const float* b1  = (const float*)d_in[3];
    const float* W2  = (const float*)d_in[4];
    const float* b2  = (const float*)d_in[5];
    const float* W3  = (const float*)d_in[6];
    const float* b3  = (const float*)d_in[7];
    const float* Wf1 = (const float*)d_in[8];
    const float* bf1 = (const float*)d_in[9];
    const float* Wf2 = (const float*)d_in[10];
    const float* bf2 = (const float*)d_in[11];
    float* out = (float*)d_out;

    float *h1, *h2;
    cudaGetSymbolAddress((void**)&h1, g_h1);
    cudaGetSymbolAddress((void**)&h2, g_h2);

    build_edges_kernel<<<TOTAL_NODES / 8, 256>>>(adj);
    gcn_layer_kernel<NDIM, true,  true,  false><<<TOTAL_NODES / 64, 256>>>(x,  W1, b1, h1);
    gcn_layer_kernel<HID,  false, true,  false><<<TOTAL_NODES / 64, 256>>>(h1, W2, b2, h2);
    gcn_layer_kernel<HID,  false, false, true ><<<TOTAL_NODES / 64, 256>>>(h2, W3, b3, h1);
    head_kernel<<<BATCH, 128>>>(Wf1, bf1, Wf2, bf2, out);
}

// round 5
// speedup vs baseline: 1.0961x; 1.0961x over previous
#include <cuda_runtime.h>
#include <cuda_bf16.h>
#include <cstdint>

#define BATCH 32
#define NN    1024
#define NDIM  14
#define HID   64
#define HEAD  128
#define MAXD  64
#define TOTAL_NODES (BATCH * NN)   // 32768

// ---------------- device scratch ----------------
__device__ int   g_nbr[TOTAL_NODES * MAXD];
__device__ int   g_cnt[TOTAL_NODES];
__device__ float g_dinv[TOTAL_NODES];
__device__ float g_h1[TOTAL_NODES * HID];
__device__ float g_h2[TOTAL_NODES * HID];
__device__ float g_pool[(TOTAL_NODES / 64) * HID];   // one partial per 64-node block

// ---------------- 1) adjacency scan (float4, warp per row) ----------------
__global__ void build_edges_kernel(const float* __restrict__ adj) {
    int row  = blockIdx.x * 8 + (threadIdx.x >> 5);
    int lane = threadIdx.x & 31;
    if (row >= TOTAL_NODES) return;

    const float4* arow = (const float4*)(adj + (size_t)row * NN);
    int* nl = &g_nbr[(size_t)row * MAXD];
    int cnt = 0;
    const unsigned lt = (1u << lane) - 1u;

    #pragma unroll
    for (int s = 0; s < NN / 128; s++) {           // 8 iterations
        float4 v = arow[s * 32 + lane];
        bool b0 = v.x > 0.5f, b1 = v.y > 0.5f, b2 = v.z > 0.5f, b3 = v.w > 0.5f;
        unsigned m0 = __ballot_sync(0xffffffffu, b0);
        unsigned m1 = __ballot_sync(0xffffffffu, b1);
        unsigned m2 = __ballot_sync(0xffffffffu, b2);
        unsigned m3 = __ballot_sync(0xffffffffu, b3);
        int prior = __popc(m0 & lt) + __popc(m1 & lt) + __popc(m2 & lt) + __popc(m3 & lt);
        int colbase = s * 128 + lane * 4;
        int p = cnt + prior;
        if (b0) { if (p < MAXD) nl[p] = colbase + 0; p++; }
        if (b1) { if (p < MAXD) nl[p] = colbase + 1; p++; }
        if (b2) { if (p < MAXD) nl[p] = colbase + 2; p++; }
        if (b3) { if (p < MAXD) nl[p] = colbase + 3; }
        cnt += __popc(m0) + __popc(m1) + __popc(m2) + __popc(m3);
    }
    if (lane == 0) {
        g_cnt[row]  = cnt < MAXD ? cnt : MAXD;
        g_dinv[row] = rsqrtf((float)cnt);
    }
}

// ---------------- 2) fused sparse-gather + GEMM + bias + ReLU ----------------
// SCALE_IN : multiply gathered rows by dinv_j (layer 1 only).
// SCALE_OUT: write dinv_i * relu(...) (layers 1,2).
// POOL     : also emit block-level column sums of the unscaled relu outputs
//            into g_pool[blockIdx.x] (layer 3).
template <int DIN, bool SCALE_IN, bool SCALE_OUT, bool POOL>
__global__ __launch_bounds__(256)
void gcn_layer_kernel(const float* __restrict__ in,
                      const float* __restrict__ W,
                      const float* __restrict__ bias,
                      float* __restrict__ out) {
    constexpr int KPAD = (DIN + 3) & ~3;
    __shared__ float Ag[64][68];          // gathered tile (node-major)
    __shared__ float Ws[KPAD][64];
    __shared__ float bs[64];

    const int tid       = threadIdx.x;
    const int blockBase = blockIdx.x * 64;
    const int bbase     = blockBase & ~(NN - 1);

    for (int i = tid; i < KPAD * 64; i += 256) {
        int r = i >> 6;
        Ws[r][i & 63] = (r < DIN) ? W[r * 64 + (i & 63)] : 0.0f;
    }
    if (tid < 64) bs[tid] = bias[tid];

    // ---- Phase A: gather, 16 threads/node, nodes sequential, j unrolled x4 ----
    {
        const int grp  = tid >> 4;   // 0..15
        const int lane = tid & 15;   // 0..15

        #pragma unroll
        for (int s = 0; s < 4; s++) {
            const int n    = grp * 4 + s;
            const int node = blockBase + n;
            const int cnt  = g_cnt[node];
            const int* nl  = &g_nbr[(size_t)node * MAXD];

            if (DIN == 64) {
                float4 acc = make_float4(0.f, 0.f, 0.f, 0.f);
                int j = 0;
                for (; j + 4 <= cnt; j += 4) {
                    const int4 idx = *(const int4*)&nl[j];     // 16B-aligned
                    const float4 v0 = *(const float4*)(in + (size_t)(bbase + idx.x) * 64 + lane * 4);
                    const float4 v1 = *(const float4*)(in + (size_t)(bbase + idx.y) * 64 + lane * 4);
                    const float4 v2 = *(const float4*)(in + (size_t)(bbase + idx.z) * 64 + lane * 4);
                    const float4 v3 = *(const float4*)(in + (size_t)(bbase + idx.w) * 64 + lane * 4);
                    if (SCALE_IN) {
                        const float d0 = g_dinv[bbase + idx.x], d1 = g_dinv[bbase + idx.y];
                        const float d2 = g_dinv[bbase + idx.z], d3 = g_dinv[bbase + idx.w];
                        acc.x += d0 * v0.x + d1 * v1.x + d2 * v2.x + d3 * v3.x;
                        acc.y += d0 * v0.y + d1 * v1.y + d2 * v2.y + d3 * v3.y;
                        acc.z += d0 * v0.z + d1 * v1.z + d2 * v2.z + d3 * v3.z;
                        acc.w += d0 * v0.w + d1 * v1.w + d2 * v2.w + d3 * v3.w;
                    } else {
                        acc.x += (v0.x + v1.x) + (v2.x + v3.x);
                        acc.y += (v0.y + v1.y) + (v2.y + v3.y);
                        acc.z += (v0.z + v1.z) + (v2.z + v3.z);
                        acc.w += (v0.w + v1.w) + (v2.w + v3.w);
                    }
                }
                for (; j < cnt; j++) {
                    const int jj = nl[j];
                    const float4 v = *(const float4*)(in + (size_t)(bbase + jj) * 64 + lane * 4);
                    const float d = SCALE_IN ? g_dinv[bbase + jj] : 1.0f;
                    acc.x += d * v.x; acc.y += d * v.y;
                    acc.z += d * v.z; acc.w += d * v.w;
                }
                const float di = g_dinv[node];
                acc.x *= di; acc.y *= di; acc.z *= di; acc.w *= di;
                *(float4*)&Ag[n][lane * 4] = acc;
            } else {
                // DIN = 14: lanes 0..13 each own one k; lanes 14,15 pad zeros
                if (lane < DIN) {
                    float acc = 0.0f;
                    int j = 0;
                    for (; j + 4 <= cnt; j += 4) {
                        const int4 idx = *(const int4*)&nl[j];
                        const float v0 = in[(size_t)(bbase + idx.x) * DIN + lane];
                        const float v1 = in[(size_t)(bbase + idx.y) * DIN + lane];
                        const float v2 = in[(size_t)(bbase + idx.z) * DIN + lane];
                        const float v3 = in[(size_t)(bbase + idx.w) * DIN + lane];
                        if (SCALE_IN) {
                            acc += g_dinv[bbase + idx.x] * v0 + g_dinv[bbase + idx.y] * v1
                                 + g_dinv[bbase + idx.z] * v2 + g_dinv[bbase + idx.w] * v3;
                        } else {
                            acc += (v0 + v1) + (v2 + v3);
                        }
                    }
                    for (; j < cnt; j++) {
                        const int jj = nl[j];
                        const float d = SCALE_IN ? g_dinv[bbase + jj] : 1.0f;
                        acc += d * in[(size_t)(bbase + jj) * DIN + lane];
                    }
                    Ag[n][lane] = g_dinv[node] * acc;
                } else if (lane < KPAD) {
                    Ag[n][lane] = 0.0f;
                }
            }
        }
    }
    __syncthreads();

    // ---- Phase B: [64 x KPAD] @ [KPAD x 64], 4x4 microtiles ----
    {
        const int tx = tid & 15;
        const int ty = tid >> 4;
        float c[4][4];
        #pragma unroll
        for (int i = 0; i < 4; i++)
            #pragma unroll
            for (int j = 0; j < 4; j++) c[i][j] = 0.0f;

        #pragma unroll
        for (int kk = 0; kk < KPAD; kk += 4) {
            float4 a[4], b[4];
            #pragma unroll
            for (int i = 0; i < 4; i++) a[i] = *(const float4*)&Ag[ty * 4 + i][kk];
            #pragma unroll
            for (int q = 0; q < 4; q++) b[q] = *(const float4*)&Ws[kk + q][tx * 4];
            #pragma unroll
            for (int i = 0; i < 4; i++) {
                const float ai[4] = {a[i].x, a[i].y, a[i].z, a[i].w};
                #pragma unroll
                for (int q = 0; q < 4; q++) {
                    c[i][0] = fmaf(ai[q], b[q].x, c[i][0]);
                    c[i][1] = fmaf(ai[q], b[q].y, c[i][1]);
                    c[i][2] = fmaf(ai[q], b[q].z, c[i][2]);
                    c[i][3] = fmaf(ai[q], b[q].w, c[i][3]);
                }
            }
        }

        float colsum[4] = {0.f, 0.f, 0.f, 0.f};
        #pragma unroll
        for (int i = 0; i < 4; i++) {
            const int row = blockBase + ty * 4 + i;
            const float dscale = SCALE_OUT ? g_dinv[row] : 1.0f;
            float4 o;
            o.x = fmaxf(c[i][0] + bs[tx * 4 + 0], 0.0f);
            o.y = fmaxf(c[i][1] + bs[tx * 4 + 1], 0.0f);
            o.z = fmaxf(c[i][2] + bs[tx * 4 + 2], 0.0f);
            o.w = fmaxf(c[i][3] + bs[tx * 4 + 3], 0.0f);
            if (POOL) {
                colsum[0] += o.x; colsum[1] += o.y;
                colsum[2] += o.z; colsum[3] += o.w;
            }
            o.x *= dscale; o.y *= dscale; o.z *= dscale; o.w *= dscale;
            *(float4*)&out[(size_t)row * 64 + tx * 4] = o;
        }

        if (POOL) {
            __syncthreads();               // done reading Ag; reuse it
            #pragma unroll
            for (int q = 0; q < 4; q++) Ag[ty][tx * 4 + q] = colsum[q];
            __syncthreads();
            if (tid < 64) {
                float s = 0.0f;
                #pragma unroll
                for (int r = 0; r < 16; r++) s += Ag[r][tid];
                g_pool[blockIdx.x * HID + tid] = s;
            }
        }
    }
}

// ---------------- 3) head: combine partials + MLP ----------------
__global__ void head_kernel(const float* __restrict__ Wf1,
                            const float* __restrict__ bf1,
                            const float* __restrict__ Wf2,
                            const float* __restrict__ bf2,
                            float* __restrict__ out) {
    const int b = blockIdx.x, tid = threadIdx.x;
    __shared__ float pooled[64];
    __shared__ float red[128];

    if (tid < 64) {
        float s = 0.0f;
        #pragma unroll
        for (int c = 0; c < 16; c++) s += g_pool[(b * 16 + c) * HID + tid];
        pooled[tid] = s * (1.0f / (float)NN);
    }
    __syncthreads();

    float a = bf1[tid];
    #pragma unroll
    for (int kk = 0; kk < 64; kk++) a = fmaf(pooled[kk], Wf1[kk * HEAD + tid], a);
    red[tid] = fmaxf(a, 0.0f) * Wf2[tid];
    __syncthreads();
    for (int off = 64; off > 0; off >>= 1) {
        if (tid < off) red[tid] += red[tid + off];
        __syncthreads();
    }
    if (tid == 0) out[b] = red[0] + bf2[0];
}

// ---------------- launch ----------------
extern "C" void kernel_launch(void* const* d_in, const int* in_sizes, int n_in,
                              void* d_out, int out_size) {
    const float* x   = (const float*)d_in[0];
    const float* adj = (const float*)d_in[1];
    const float* W1  = (const float*)d_in[2];
    const float* b1  = (const float*)d_in[3];
    const float* W2  = (const float*)d_in[4];
    const float* b2  = (const float*)d_in[5];
    const float* W3  = (const float*)d_in[6];
    const float* b3  = (const float*)d_in[7];
    const float* Wf1 = (const float*)d_in[8];
    const float* bf1 = (const float*)d_in[9];
    const float* Wf2 = (const float*)d_in[10];
    const float* bf2 = (const float*)d_in[11];
    float* out = (float*)d_out;

    float *h1, *h2;
    cudaGetSymbolAddress((void**)&h1, g_h1);
    cudaGetSymbolAddress((void**)&h2, g_h2);

    build_edges_kernel<<<TOTAL_NODES / 8, 256>>>(adj);
    gcn_layer_kernel<NDIM, true,  true,  false><<<TOTAL_NODES / 64, 256>>>(x,  W1, b1, h1);
    gcn_layer_kernel<HID,  false, true,  false><<<TOTAL_NODES / 64, 256>>>(h1, W2, b2, h2);
    gcn_layer_kernel<HID,  false, false, true ><<<TOTAL_NODES / 64, 256>>>(h2, W3, b3, h1);
    head_kernel<<<BATCH, 128>>>(Wf1, bf1, Wf2, bf2, out);
}

// round 6
// speedup vs baseline: 1.2364x; 1.1280x over previous
#include <cuda_runtime.h>
#include <cuda_bf16.h>
#include <cstdint>

#define BATCH 32
#define NN    1024
#define NDIM  14
#define HID   64
#define HEAD  128
#define MAXD  64
#define TOTAL_NODES (BATCH * NN)   // 32768
#define NODES_PER_BLK 32
#define NBLK (TOTAL_NODES / NODES_PER_BLK)   // 1024

// ---------------- device scratch ----------------
__device__ int   g_nbr[TOTAL_NODES * MAXD];
__device__ int   g_cnt[TOTAL_NODES];
__device__ float g_dinv[TOTAL_NODES];
__device__ float g_h1[TOTAL_NODES * HID];
__device__ float g_h2[TOTAL_NODES * HID];
__device__ float g_pool[NBLK * HID];          // one partial per 32-node block

// ---------------- 1) adjacency scan (float4, warp per row) ----------------
__global__ void build_edges_kernel(const float* __restrict__ adj) {
    int row  = blockIdx.x * 8 + (threadIdx.x >> 5);
    int lane = threadIdx.x & 31;
    if (row >= TOTAL_NODES) return;

    const float4* arow = (const float4*)(adj + (size_t)row * NN);
    int* nl = &g_nbr[(size_t)row * MAXD];
    int cnt = 0;
    const unsigned lt = (1u << lane) - 1u;

    #pragma unroll
    for (int s = 0; s < NN / 128; s++) {           // 8 iterations
        float4 v = arow[s * 32 + lane];
        bool b0 = v.x > 0.5f, b1 = v.y > 0.5f, b2 = v.z > 0.5f, b3 = v.w > 0.5f;
        unsigned m0 = __ballot_sync(0xffffffffu, b0);
        unsigned m1 = __ballot_sync(0xffffffffu, b1);
        unsigned m2 = __ballot_sync(0xffffffffu, b2);
        unsigned m3 = __ballot_sync(0xffffffffu, b3);
        int prior = __popc(m0 & lt) + __popc(m1 & lt) + __popc(m2 & lt) + __popc(m3 & lt);
        int colbase = s * 128 + lane * 4;
        int p = cnt + prior;
        if (b0) { if (p < MAXD) nl[p] = colbase + 0; p++; }
        if (b1) { if (p < MAXD) nl[p] = colbase + 1; p++; }
        if (b2) { if (p < MAXD) nl[p] = colbase + 2; p++; }
        if (b3) { if (p < MAXD) nl[p] = colbase + 3; }
        cnt += __popc(m0) + __popc(m1) + __popc(m2) + __popc(m3);
    }
    if (lane == 0) {
        g_cnt[row]  = cnt < MAXD ? cnt : MAXD;
        g_dinv[row] = rsqrtf((float)cnt);
    }
}

// ---------------- 2) fused sparse-gather + GEMM + bias + ReLU ----------------
// 128 threads per block, 32 nodes per block (fine-grained for occupancy).
// SCALE_IN : multiply gathered rows by dinv_j (layer 1 only).
// SCALE_OUT: write dinv_i * relu(...) (layers 1,2).
// POOL     : emit block-level column sums of unscaled relu outputs (layer 3).
template <int DIN, bool SCALE_IN, bool SCALE_OUT, bool POOL>
__global__ __launch_bounds__(128)
void gcn_layer_kernel(const float* __restrict__ in,
                      const float* __restrict__ W,
                      const float* __restrict__ bias,
                      float* __restrict__ out) {
    constexpr int KPAD = (DIN + 3) & ~3;
    __shared__ float Ag[NODES_PER_BLK][68];   // gathered tile (node-major)
    __shared__ float Ws[KPAD][64];
    __shared__ float bs[64];

    const int tid       = threadIdx.x;
    const int blockBase = blockIdx.x * NODES_PER_BLK;
    const int bbase     = blockBase & ~(NN - 1);

    if (DIN == 64) {
        #pragma unroll
        for (int i = tid; i < DIN * 16; i += 128)
            ((float4*)Ws)[i] = ((const float4*)W)[i];
    } else {
        for (int i = tid; i < KPAD * 64; i += 128) {
            int r = i >> 6;
            Ws[r][i & 63] = (r < DIN) ? W[r * 64 + (i & 63)] : 0.0f;
        }
    }
    if (tid < 64) bs[tid] = bias[tid];

    // ---- Phase A: gather, 16 threads/node, nodes sequential, j unrolled x4 ----
    {
        const int grp  = tid >> 4;   // 0..7
        const int lane = tid & 15;   // 0..15

        #pragma unroll
        for (int s = 0; s < 4; s++) {
            const int n    = grp * 4 + s;
            const int node = blockBase + n;
            const int cnt  = g_cnt[node];
            const int* nl  = &g_nbr[(size_t)node * MAXD];

            if (DIN == 64) {
                float4 acc = make_float4(0.f, 0.f, 0.f, 0.f);
                int j = 0;
                for (; j + 4 <= cnt; j += 4) {
                    const int4 idx = *(const int4*)&nl[j];     // 16B-aligned
                    const float4 v0 = *(const float4*)(in + (size_t)(bbase + idx.x) * 64 + lane * 4);
                    const float4 v1 = *(const float4*)(in + (size_t)(bbase + idx.y) * 64 + lane * 4);
                    const float4 v2 = *(const float4*)(in + (size_t)(bbase + idx.z) * 64 + lane * 4);
                    const float4 v3 = *(const float4*)(in + (size_t)(bbase + idx.w) * 64 + lane * 4);
                    if (SCALE_IN) {
                        const float d0 = g_dinv[bbase + idx.x], d1 = g_dinv[bbase + idx.y];
                        const float d2 = g_dinv[bbase + idx.z], d3 = g_dinv[bbase + idx.w];
                        acc.x += d0 * v0.x + d1 * v1.x + d2 * v2.x + d3 * v3.x;
                        acc.y += d0 * v0.y + d1 * v1.y + d2 * v2.y + d3 * v3.y;
                        acc.z += d0 * v0.z + d1 * v1.z + d2 * v2.z + d3 * v3.z;
                        acc.w += d0 * v0.w + d1 * v1.w + d2 * v2.w + d3 * v3.w;
                    } else {
                        acc.x += (v0.x + v1.x) + (v2.x + v3.x);
                        acc.y += (v0.y + v1.y) + (v2.y + v3.y);
                        acc.z += (v0.z + v1.z) + (v2.z + v3.z);
                        acc.w += (v0.w + v1.w) + (v2.w + v3.w);
                    }
                }
                if (j + 2 <= cnt) {
                    const int j0 = nl[j], j1 = nl[j + 1];
                    const float4 v0 = *(const float4*)(in + (size_t)(bbase + j0) * 64 + lane * 4);
                    const float4 v1 = *(const float4*)(in + (size_t)(bbase + j1) * 64 + lane * 4);
                    const float d0 = SCALE_IN ? g_dinv[bbase + j0] : 1.0f;
                    const float d1 = SCALE_IN ? g_dinv[bbase + j1] : 1.0f;
                    acc.x += d0 * v0.x + d1 * v1.x;
                    acc.y += d0 * v0.y + d1 * v1.y;
                    acc.z += d0 * v0.z + d1 * v1.z;
                    acc.w += d0 * v0.w + d1 * v1.w;
                    j += 2;
                }
                if (j < cnt) {
                    const int jj = nl[j];
                    const float4 v = *(const float4*)(in + (size_t)(bbase + jj) * 64 + lane * 4);
                    const float d = SCALE_IN ? g_dinv[bbase + jj] : 1.0f;
                    acc.x += d * v.x; acc.y += d * v.y;
                    acc.z += d * v.z; acc.w += d * v.w;
                }
                const float di = g_dinv[node];
                acc.x *= di; acc.y *= di; acc.z *= di; acc.w *= di;
                *(float4*)&Ag[n][lane * 4] = acc;
            } else {
                // DIN = 14: lanes 0..13 each own one k; lanes 14,15 pad zeros
                if (lane < DIN) {
                    float acc = 0.0f;
                    int j = 0;
                    for (; j + 4 <= cnt; j += 4) {
                        const int4 idx = *(const int4*)&nl[j];
                        const float v0 = in[(size_t)(bbase + idx.x) * DIN + lane];
                        const float v1 = in[(size_t)(bbase + idx.y) * DIN + lane];
                        const float v2 = in[(size_t)(bbase + idx.z) * DIN + lane];
                        const float v3 = in[(size_t)(bbase + idx.w) * DIN + lane];
                        if (SCALE_IN) {
                            acc += g_dinv[bbase + idx.x] * v0 + g_dinv[bbase + idx.y] * v1
                                 + g_dinv[bbase + idx.z] * v2 + g_dinv[bbase + idx.w] * v3;
                        } else {
                            acc += (v0 + v1) + (v2 + v3);
                        }
                    }
                    for (; j < cnt; j++) {
                        const int jj = nl[j];
                        const float d = SCALE_IN ? g_dinv[bbase + jj] : 1.0f;
                        acc += d * in[(size_t)(bbase + jj) * DIN + lane];
                    }
                    Ag[n][lane] = g_dinv[node] * acc;
                } else if (lane < KPAD) {
                    Ag[n][lane] = 0.0f;
                }
            }
        }
    }
    __syncthreads();

    // ---- Phase B: [32 x KPAD] @ [KPAD x 64], 4x4 microtiles ----
    {
        const int tx = tid & 15;    // col group (4 cols)
        const int ty = tid >> 4;    // row group (4 rows), 0..7 -> 32 rows
        float c[4][4];
        #pragma unroll
        for (int i = 0; i < 4; i++)
            #pragma unroll
            for (int j = 0; j < 4; j++) c[i][j] = 0.0f;

        #pragma unroll
        for (int kk = 0; kk < KPAD; kk += 4) {
            float4 a[4], b[4];
            #pragma unroll
            for (int i = 0; i < 4; i++) a[i] = *(const float4*)&Ag[ty * 4 + i][kk];
            #pragma unroll
            for (int q = 0; q < 4; q++) b[q] = *(const float4*)&Ws[kk + q][tx * 4];
            #pragma unroll
            for (int i = 0; i < 4; i++) {
                const float ai[4] = {a[i].x, a[i].y, a[i].z, a[i].w};
                #pragma unroll
                for (int q = 0; q < 4; q++) {
                    c[i][0] = fmaf(ai[q], b[q].x, c[i][0]);
                    c[i][1] = fmaf(ai[q], b[q].y, c[i][1]);
                    c[i][2] = fmaf(ai[q], b[q].z, c[i][2]);
                    c[i][3] = fmaf(ai[q], b[q].w, c[i][3]);
                }
            }
        }

        float colsum[4] = {0.f, 0.f, 0.f, 0.f};
        #pragma unroll
        for (int i = 0; i < 4; i++) {
            const int row = blockBase + ty * 4 + i;
            const float dscale = SCALE_OUT ? g_dinv[row] : 1.0f;
            float4 o;
            o.x = fmaxf(c[i][0] + bs[tx * 4 + 0], 0.0f);
            o.y = fmaxf(c[i][1] + bs[tx * 4 + 1], 0.0f);
            o.z = fmaxf(c[i][2] + bs[tx * 4 + 2], 0.0f);
            o.w = fmaxf(c[i][3] + bs[tx * 4 + 3], 0.0f);
            if (POOL) {
                colsum[0] += o.x; colsum[1] += o.y;
                colsum[2] += o.z; colsum[3] += o.w;
            }
            o.x *= dscale; o.y *= dscale; o.z *= dscale; o.w *= dscale;
            *(float4*)&out[(size_t)row * 64 + tx * 4] = o;
        }

        if (POOL) {
            __syncthreads();               // done reading Ag; reuse it
            #pragma unroll
            for (int q = 0; q < 4; q++) Ag[ty][tx * 4 + q] = colsum[q];
            __syncthreads();
            if (tid < 64) {
                float s = 0.0f;
                #pragma unroll
                for (int r = 0; r < 8; r++) s += Ag[r][tid];
                g_pool[blockIdx.x * HID + tid] = s;
            }
        }
    }
}

// ---------------- 3) head: combine partials + MLP ----------------
__global__ void head_kernel(const float* __restrict__ Wf1,
                            const float* __restrict__ bf1,
                            const float* __restrict__ Wf2,
                            const float* __restrict__ bf2,
                            float* __restrict__ out) {
    const int b = blockIdx.x, tid = threadIdx.x;
    const int chunks = NN / NODES_PER_BLK;   // 32 partials per batch
    __shared__ float pooled[64];
    __shared__ float red[128];

    if (tid < 64) {
        float s = 0.0f;
        #pragma unroll
        for (int c = 0; c < chunks; c++) s += g_pool[(b * chunks + c) * HID + tid];
        pooled[tid] = s * (1.0f / (float)NN);
    }
    __syncthreads();

    float a = bf1[tid];
    #pragma unroll
    for (int kk = 0; kk < 64; kk++) a = fmaf(pooled[kk], Wf1[kk * HEAD + tid], a);
    red[tid] = fmaxf(a, 0.0f) * Wf2[tid];
    __syncthreads();
    for (int off = 64; off > 0; off >>= 1) {
        if (tid < off) red[tid] += red[tid + off];
        __syncthreads();
    }
    if (tid == 0) out[b] = red[0] + bf2[0];
}

// ---------------- launch ----------------
extern "C" void kernel_launch(void* const* d_in, const int* in_sizes, int n_in,
                              void* d_out, int out_size) {
    const float* x   = (const float*)d_in[0];
    const float* adj = (const float*)d_in[1];
    const float* W1  = (const float*)d_in[2];
    const float* b1  = (const float*)d_in[3];
    const float* W2  = (const float*)d_in[4];
    const float* b2  = (const float*)d_in[5];
    const float* W3  = (const float*)d_in[6];
    const float* b3  = (const float*)d_in[7];
    const float* Wf1 = (const float*)d_in[8];
    const float* bf1 = (const float*)d_in[9];
    const float* Wf2 = (const float*)d_in[10];
    const float* bf2 = (const float*)d_in[11];
    float* out = (float*)d_out;

    float *h1, *h2;
    cudaGetSymbolAddress((void**)&h1, g_h1);
    cudaGetSymbolAddress((void**)&h2, g_h2);

    build_edges_kernel<<<TOTAL_NODES / 8, 256>>>(adj);
    gcn_layer_kernel<NDIM, true,  true,  false><<<NBLK, 128>>>(x,  W1, b1, h1);
    gcn_layer_kernel<HID,  false, true,  false><<<NBLK, 128>>>(h1, W2, b2, h2);
    gcn_layer_kernel<HID,  false, false, true ><<<NBLK, 128>>>(h2, W3, b3, h1);
    head_kernel<<<BATCH, 128>>>(Wf1, bf1, Wf2, bf2, out);
}

// round 10
// speedup vs baseline: 1.2606x; 1.0196x over previous
#include <cuda_runtime.h>
#include <cuda_bf16.h>
#include <cstdint>

#define BATCH 32
#define NN    1024
#define NDIM  14
#define HID   64
#define HEAD  128
#define MAXD  64
#define TOTAL_NODES (BATCH * NN)   // 32768
#define NODES_PER_BLK 32
#define NBLK (TOTAL_NODES / NODES_PER_BLK)   // 1024

static_assert(TOTAL_NODES % NODES_PER_BLK == 0, "block tiling");
static_assert(NN % 128 == 0, "adjacency scan tiling");

// ---------------- device scratch ----------------
__device__ int           g_nbr[TOTAL_NODES * MAXD];
__device__ int           g_cnt[TOTAL_NODES];
__device__ float         g_dinv[TOTAL_NODES];
__device__ __nv_bfloat16 g_h1[TOTAL_NODES * HID];   // bf16 activations
__device__ __nv_bfloat16 g_h2[TOTAL_NODES * HID];
__device__ float         g_pool[NBLK * HID];        // fp32 partial pools

// ---------------- 1) adjacency scan (float4, warp per row) ----------------
__global__ void build_edges_kernel(const float* __restrict__ adj) {
    int row  = blockIdx.x * 8 + (threadIdx.x >> 5);
    int lane = threadIdx.x & 31;
    if (row >= TOTAL_NODES) return;

    const float4* arow = (const float4*)(adj + (size_t)row * NN);
    int* nl = &g_nbr[(size_t)row * MAXD];
    int cnt = 0;
    const unsigned lt = (1u << lane) - 1u;

    #pragma unroll
    for (int s = 0; s < NN / 128; s++) {           // 8 iterations
        float4 v = arow[s * 32 + lane];
        bool b0 = v.x > 0.5f, b1 = v.y > 0.5f, b2 = v.z > 0.5f, b3 = v.w > 0.5f;
        unsigned m0 = __ballot_sync(0xffffffffu, b0);
        unsigned m1 = __ballot_sync(0xffffffffu, b1);
        unsigned m2 = __ballot_sync(0xffffffffu, b2);
        unsigned m3 = __ballot_sync(0xffffffffu, b3);
        int prior = __popc(m0 & lt) + __popc(m1 & lt) + __popc(m2 & lt) + __popc(m3 & lt);
        int colbase = s * 128 + lane * 4;
        int p = cnt + prior;
        if (b0) { if (p < MAXD) nl[p] = colbase + 0; p++; }
        if (b1) { if (p < MAXD) nl[p] = colbase + 1; p++; }
        if (b2) { if (p < MAXD) nl[p] = colbase + 2; p++; }
        if (b3) { if (p < MAXD) nl[p] = colbase + 3; }
        cnt += __popc(m0) + __popc(m1) + __popc(m2) + __popc(m3);
    }
    if (lane == 0) {
        g_cnt[row]  = cnt < MAXD ? cnt : MAXD;
        g_dinv[row] = rsqrtf((float)cnt);
    }
}

// helper: load 4 bf16 (8B) and widen to float4
__device__ __forceinline__ float4 ld_bf16x4(const __nv_bfloat16* p) {
    uint2 raw = *(const uint2*)p;
    __nv_bfloat162 p0 = *reinterpret_cast<const __nv_bfloat162*>(&raw.x);
    __nv_bfloat162 p1 = *reinterpret_cast<const __nv_bfloat162*>(&raw.y);
    float2 f0 = __bfloat1622float2(p0);
    float2 f1 = __bfloat1622float2(p1);
    return make_float4(f0.x, f0.y, f1.x, f1.y);
}

// ---------------- 2) fused sparse-gather + GEMM + bias + ReLU ----------------
// 128 threads / 32 nodes per block.
// TIN      : float (layer 1, DIN=14) or __nv_bfloat16 (layers 2,3, DIN=64).
// SCALE_IN : multiply gathered rows by dinv_j (layer 1 only).
// SCALE_OUT: write dinv_i * relu(...) (layers 1,2).
// POOL     : emit block column-sums of relu outputs; SKIP per-node store (layer 3).
template <int DIN, typename TIN, bool SCALE_IN, bool SCALE_OUT, bool POOL>
__global__ __launch_bounds__(128)
void gcn_layer_kernel(const TIN* __restrict__ in,
                      const float* __restrict__ W,
                      const float* __restrict__ bias,
                      __nv_bfloat16* __restrict__ out) {
    constexpr int KPAD = (DIN + 3) & ~3;
    __shared__ float Ag[NODES_PER_BLK][68];   // gathered tile (node-major)
    __shared__ float Ws[KPAD][64];
    __shared__ float bs[64];

    const int tid       = threadIdx.x;
    const int blockBase = blockIdx.x * NODES_PER_BLK;
    const int bbase     = blockBase & ~(NN - 1);

    if (DIN == 64) {
        #pragma unroll
        for (int i = tid; i < DIN * 16; i += 128)
            ((float4*)Ws)[i] = ((const float4*)W)[i];
    } else {
        for (int i = tid; i < KPAD * 64; i += 128) {
            int r = i >> 6;
            Ws[r][i & 63] = (r < DIN) ? W[r * 64 + (i & 63)] : 0.0f;
        }
    }
    if (tid < 64) bs[tid] = bias[tid];

    // ---- Phase A: gather, 16 threads/node, j unrolled x4 ----
    {
        const int grp  = tid >> 4;   // 0..7
        const int lane = tid & 15;   // 0..15

        #pragma unroll
        for (int s = 0; s < 4; s++) {
            const int n    = grp * 4 + s;
            const int node = blockBase + n;
            const int cnt  = g_cnt[node];
            const int* nl  = &g_nbr[(size_t)node * MAXD];

            if (DIN == 64) {
                float4 acc = make_float4(0.f, 0.f, 0.f, 0.f);
                int j = 0;
                for (; j + 4 <= cnt; j += 4) {
                    const int4 idx = *(const int4*)&nl[j];
                    const float4 v0 = ld_bf16x4((const __nv_bfloat16*)in + (size_t)(bbase + idx.x) * 64 + lane * 4);
                    const float4 v1 = ld_bf16x4((const __nv_bfloat16*)in + (size_t)(bbase + idx.y) * 64 + lane * 4);
                    const float4 v2 = ld_bf16x4((const __nv_bfloat16*)in + (size_t)(bbase + idx.z) * 64 + lane * 4);
                    const float4 v3 = ld_bf16x4((const __nv_bfloat16*)in + (size_t)(bbase + idx.w) * 64 + lane * 4);
                    acc.x += (v0.x + v1.x) + (v2.x + v3.x);
                    acc.y += (v0.y + v1.y) + (v2.y + v3.y);
                    acc.z += (v0.z + v1.z) + (v2.z + v3.z);
                    acc.w += (v0.w + v1.w) + (v2.w + v3.w);
                }
                if (j + 2 <= cnt) {
                    const int j0 = nl[j], j1 = nl[j + 1];
                    const float4 v0 = ld_bf16x4((const __nv_bfloat16*)in + (size_t)(bbase + j0) * 64 + lane * 4);
                    const float4 v1 = ld_bf16x4((const __nv_bfloat16*)in + (size_t)(bbase + j1) * 64 + lane * 4);
                    acc.x += v0.x + v1.x; acc.y += v0.y + v1.y;
                    acc.z += v0.z + v1.z; acc.w += v0.w + v1.w;
                    j += 2;
                }
                if (j < cnt) {
                    const int jj = nl[j];
                    const float4 v = ld_bf16x4((const __nv_bfloat16*)in + (size_t)(bbase + jj) * 64 + lane * 4);
                    acc.x += v.x; acc.y += v.y; acc.z += v.z; acc.w += v.w;
                }
                const float di = g_dinv[node];
                acc.x *= di; acc.y *= di; acc.z *= di; acc.w *= di;
                *(float4*)&Ag[n][lane * 4] = acc;
            } else {
                // DIN = 14 (fp32 input): lanes 0..13 own one k each
                if (lane < DIN) {
                    const float* fin = (const float*)in;
                    float acc = 0.0f;
                    int j = 0;
                    for (; j + 4 <= cnt; j += 4) {
                        const int4 idx = *(const int4*)&nl[j];
                        const float v0 = fin[(size_t)(bbase + idx.x) * DIN + lane];
                        const float v1 = fin[(size_t)(bbase + idx.y) * DIN + lane];
                        const float v2 = fin[(size_t)(bbase + idx.z) * DIN + lane];
                        const float v3 = fin[(size_t)(bbase + idx.w) * DIN + lane];
                        if (SCALE_IN) {
                            acc += g_dinv[bbase + idx.x] * v0 + g_dinv[bbase + idx.y] * v1
                                 + g_dinv[bbase + idx.z] * v2 + g_dinv[bbase + idx.w] * v3;
                        } else {
                            acc += (v0 + v1) + (v2 + v3);
                        }
                    }
                    for (; j < cnt; j++) {
                        const int jj = nl[j];
                        const float d = SCALE_IN ? g_dinv[bbase + jj] : 1.0f;
                        acc += d * fin[(size_t)(bbase + jj) * DIN + lane];
                    }
                    Ag[n][lane] = g_dinv[node] * acc;
                } else if (lane < KPAD) {
                    Ag[n][lane] = 0.0f;
                }
            }
        }
    }
    __syncthreads();

    // ---- Phase B: [32 x KPAD] @ [KPAD x 64], 4x4 microtiles ----
    {
        const int tx = tid & 15;
        const int ty = tid >> 4;
        float c[4][4];
        #pragma unroll
        for (int i = 0; i < 4; i++)
            #pragma unroll
            for (int j = 0; j < 4; j++) c[i][j] = 0.0f;

        #pragma unroll
        for (int kk = 0; kk < KPAD; kk += 4) {
            float4 a[4], b[4];
            #pragma unroll
            for (int i = 0; i < 4; i++) a[i] = *(const float4*)&Ag[ty * 4 + i][kk];
            #pragma unroll
            for (int q = 0; q < 4; q++) b[q] = *(const float4*)&Ws[kk + q][tx * 4];
            #pragma unroll
            for (int i = 0; i < 4; i++) {
                const float ai[4] = {a[i].x, a[i].y, a[i].z, a[i].w};
                #pragma unroll
                for (int q = 0; q < 4; q++) {
                    c[i][0] = fmaf(ai[q], b[q].x, c[i][0]);
                    c[i][1] = fmaf(ai[q], b[q].y, c[i][1]);
                    c[i][2] = fmaf(ai[q], b[q].z, c[i][2]);
                    c[i][3] = fmaf(ai[q], b[q].w, c[i][3]);
                }
            }
        }

        float colsum[4] = {0.f, 0.f, 0.f, 0.f};
        #pragma unroll
        for (int i = 0; i < 4; i++) {
            const int row = blockBase + ty * 4 + i;
            float4 o;
            o.x = fmaxf(c[i][0] + bs[tx * 4 + 0], 0.0f);
            o.y = fmaxf(c[i][1] + bs[tx * 4 + 1], 0.0f);
            o.z = fmaxf(c[i][2] + bs[tx * 4 + 2], 0.0f);
            o.w = fmaxf(c[i][3] + bs[tx * 4 + 3], 0.0f);
            if (POOL) {
                // only the block column-sums are consumed downstream
                colsum[0] += o.x; colsum[1] += o.y;
                colsum[2] += o.z; colsum[3] += o.w;
            } else {
                const float dscale = SCALE_OUT ? g_dinv[row] : 1.0f;
                union { __nv_bfloat162 h2[2]; uint2 u; } cvt;
                cvt.h2[0] = __floats2bfloat162_rn(o.x * dscale, o.y * dscale);
                cvt.h2[1] = __floats2bfloat162_rn(o.z * dscale, o.w * dscale);
                *(uint2*)&out[(size_t)row * 64 + tx * 4] = cvt.u;
            }
        }

        if (POOL) {
            __syncthreads();               // done reading Ag; reuse it
            #pragma unroll
            for (int q = 0; q < 4; q++) Ag[ty][tx * 4 + q] = colsum[q];
            __syncthreads();
            if (tid < 64) {
                float s = 0.0f;
                #pragma unroll
                for (int r = 0; r < 8; r++) s += Ag[r][tid];
                g_pool[blockIdx.x * HID + tid] = s;
            }
        }
    }
}

// ---------------- 3) head: combine partials + MLP ----------------
__global__ void head_kernel(const float* __restrict__ Wf1,
                            const float* __restrict__ bf1,
                            const float* __restrict__ Wf2,
                            const float* __restrict__ bf2,
                            float* __restrict__ out) {
    const int b = blockIdx.x, tid = threadIdx.x;
    const int chunks = NN / NODES_PER_BLK;   // 32 partials per batch
    __shared__ float pooled[64];
    __shared__ float red[128];

    if (tid < 64) {
        float s = 0.0f;
        #pragma unroll
        for (int c = 0; c < chunks; c++) s += g_pool[(b * chunks + c) * HID + tid];
        pooled[tid] = s * (1.0f / (float)NN);
    }
    __syncthreads();

    float a = bf1[tid];
    #pragma unroll
    for (int kk = 0; kk < 64; kk++) a = fmaf(pooled[kk], Wf1[kk * HEAD + tid], a);
    red[tid] = fmaxf(a, 0.0f) * Wf2[tid];
    __syncthreads();
    for (int off = 64; off > 0; off >>= 1) {
        if (tid < off) red[tid] += red[tid + off];
        __syncthreads();
    }
    if (tid == 0) out[b] = red[0] + bf2[0];
}

// ---------------- launch ----------------
extern "C" void kernel_launch(void* const* d_in, const int* in_sizes, int n_in,
                              void* d_out, int out_size) {
    const float* x   = (const float*)d_in[0];
    const float* adj = (const float*)d_in[1];
    const float* W1  = (const float*)d_in[2];
    const float* b1  = (const float*)d_in[3];
    const float* W2  = (const float*)d_in[4];
    const float* b2  = (const float*)d_in[5];
    const float* W3  = (const float*)d_in[6];
    const float* b3  = (const float*)d_in[7];
    const float* Wf1 = (const float*)d_in[8];
    const float* bf1 = (const float*)d_in[9];
    const float* Wf2 = (const float*)d_in[10];
    const float* bf2 = (const float*)d_in[11];
    float* out = (float*)d_out;

    __nv_bfloat16 *h1, *h2;
    cudaGetSymbolAddress((void**)&h1, g_h1);
    cudaGetSymbolAddress((void**)&h2, g_h2);

    build_edges_kernel<<<TOTAL_NODES / 8, 256>>>(adj);
    gcn_layer_kernel<NDIM, float,         true,  true,  false><<<NBLK, 128>>>(x,  W1, b1, h1);
    gcn_layer_kernel<HID,  __nv_bfloat16, false, true,  false><<<NBLK, 128>>>(h1, W2, b2, h2);
    gcn_layer_kernel<HID,  __nv_bfloat16, false, false, true ><<<NBLK, 128>>>(h2, W3, b3, h1);
    head_kernel<<<BATCH, 128>>>(Wf1, bf1, Wf2, bf2, out);
}

// round 11
// speedup vs baseline: 1.2904x; 1.0237x over previous
#include <cuda_runtime.h>
#include <cuda_bf16.h>
#include <cstdint>

#define BATCH 32
#define NN    1024
#define NDIM  14
#define HID   64
#define HEAD  128
#define MAXD  64
#define TOTAL_NODES (BATCH * NN)   // 32768
#define NODES_PER_BLK 32
#define NBLK (TOTAL_NODES / NODES_PER_BLK)   // 1024

static_assert(TOTAL_NODES % NODES_PER_BLK == 0, "block tiling");
static_assert(NN % 128 == 0, "adjacency scan tiling");

// ---------------- device scratch ----------------
__device__ int           g_nbr[TOTAL_NODES * MAXD];
__device__ int           g_cnt[TOTAL_NODES];
__device__ float         g_dinv[TOTAL_NODES];
__device__ __nv_bfloat16 g_xw[TOTAL_NODES * HID];   // dinv_j * (x_j @ W1)
__device__ __nv_bfloat16 g_h1[TOTAL_NODES * HID];   // bf16 activations (pre-scaled)
__device__ __nv_bfloat16 g_h2[TOTAL_NODES * HID];
__device__ float         g_pool[NBLK * HID];        // fp32 partial pools

// ---------------- 1) adjacency scan (float4, warp per row) ----------------
__global__ void build_edges_kernel(const float* __restrict__ adj) {
    int row  = blockIdx.x * 8 + (threadIdx.x >> 5);
    int lane = threadIdx.x & 31;
    if (row >= TOTAL_NODES) return;

    const float4* arow = (const float4*)(adj + (size_t)row * NN);
    int* nl = &g_nbr[(size_t)row * MAXD];
    int cnt = 0;
    const unsigned lt = (1u << lane) - 1u;

    #pragma unroll
    for (int s = 0; s < NN / 128; s++) {           // 8 iterations
        float4 v = arow[s * 32 + lane];
        bool b0 = v.x > 0.5f, b1 = v.y > 0.5f, b2 = v.z > 0.5f, b3 = v.w > 0.5f;
        unsigned m0 = __ballot_sync(0xffffffffu, b0);
        unsigned m1 = __ballot_sync(0xffffffffu, b1);
        unsigned m2 = __ballot_sync(0xffffffffu, b2);
        unsigned m3 = __ballot_sync(0xffffffffu, b3);
        int prior = __popc(m0 & lt) + __popc(m1 & lt) + __popc(m2 & lt) + __popc(m3 & lt);
        int colbase = s * 128 + lane * 4;
        int p = cnt + prior;
        if (b0) { if (p < MAXD) nl[p] = colbase + 0; p++; }
        if (b1) { if (p < MAXD) nl[p] = colbase + 1; p++; }
        if (b2) { if (p < MAXD) nl[p] = colbase + 2; p++; }
        if (b3) { if (p < MAXD) nl[p] = colbase + 3; }
        cnt += __popc(m0) + __popc(m1) + __popc(m2) + __popc(m3);
    }
    if (lane == 0) {
        g_cnt[row]  = cnt < MAXD ? cnt : MAXD;
        g_dinv[row] = rsqrtf((float)cnt);
    }
}

// accumulate 8 bf16 (one uint4) into fp32 acc[8]
__device__ __forceinline__ void acc_bf16x8(uint4 raw, float* acc) {
    float2 f;
    f = __bfloat1622float2(*reinterpret_cast<__nv_bfloat162*>(&raw.x)); acc[0] += f.x; acc[1] += f.y;
    f = __bfloat1622float2(*reinterpret_cast<__nv_bfloat162*>(&raw.y)); acc[2] += f.x; acc[3] += f.y;
    f = __bfloat1622float2(*reinterpret_cast<__nv_bfloat162*>(&raw.z)); acc[4] += f.x; acc[5] += f.y;
    f = __bfloat1622float2(*reinterpret_cast<__nv_bfloat162*>(&raw.w)); acc[6] += f.x; acc[7] += f.y;
}

// gather one node's neighbor rows (bf16, 64 cols, this lane's 8 cols) into acc[8]
__device__ __forceinline__ void gather_node(const __nv_bfloat16* __restrict__ in,
                                            const int* __restrict__ nl, int cnt,
                                            int bbase, int lane8, float* acc) {
    #pragma unroll
    for (int q = 0; q < 8; q++) acc[q] = 0.0f;
    int j = 0;
    for (; j + 4 <= cnt; j += 4) {
        const int4 idx = *(const int4*)&nl[j];
        uint4 r0 = *(const uint4*)(in + (size_t)(bbase + idx.x) * 64 + lane8 * 8);
        uint4 r1 = *(const uint4*)(in + (size_t)(bbase + idx.y) * 64 + lane8 * 8);
        uint4 r2 = *(const uint4*)(in + (size_t)(bbase + idx.z) * 64 + lane8 * 8);
        uint4 r3 = *(const uint4*)(in + (size_t)(bbase + idx.w) * 64 + lane8 * 8);
        acc_bf16x8(r0, acc); acc_bf16x8(r1, acc);
        acc_bf16x8(r2, acc); acc_bf16x8(r3, acc);
    }
    if (j + 2 <= cnt) {
        const int j0 = nl[j], j1 = nl[j + 1];
        uint4 r0 = *(const uint4*)(in + (size_t)(bbase + j0) * 64 + lane8 * 8);
        uint4 r1 = *(const uint4*)(in + (size_t)(bbase + j1) * 64 + lane8 * 8);
        acc_bf16x8(r0, acc); acc_bf16x8(r1, acc);
        j += 2;
    }
    if (j < cnt) {
        uint4 r0 = *(const uint4*)(in + (size_t)(bbase + nl[j]) * 64 + lane8 * 8);
        acc_bf16x8(r0, acc);
    }
}

// store 8 fp32 as 8 bf16 (16B)
__device__ __forceinline__ void st_bf16x8(__nv_bfloat16* p, const float* v) {
    union { __nv_bfloat162 h2[4]; uint4 u; } cvt;
    cvt.h2[0] = __floats2bfloat162_rn(v[0], v[1]);
    cvt.h2[1] = __floats2bfloat162_rn(v[2], v[3]);
    cvt.h2[2] = __floats2bfloat162_rn(v[4], v[5]);
    cvt.h2[3] = __floats2bfloat162_rn(v[6], v[7]);
    *(uint4*)p = cvt.u;
}

// ---------------- 2a) XW = dinv_j * (x_j @ W1), bf16 out ----------------
// 128 threads, 8 nodes/block, 16 threads/node (4 cols each). grid 4096.
__global__ __launch_bounds__(128)
void xw_kernel(const float* __restrict__ x,
               const float* __restrict__ W1,
               __nv_bfloat16* __restrict__ out) {
    __shared__ float Ws[NDIM][64];
    const int tid = threadIdx.x;
    for (int i = tid; i < NDIM * 64; i += 128) Ws[i >> 6][i & 63] = W1[i];
    __syncthreads();

    const int grp  = tid >> 4;       // 0..7
    const int lane = tid & 15;       // 0..15
    const int node = blockIdx.x * 8 + grp;

    float xv[NDIM];
    #pragma unroll
    for (int k = 0; k < NDIM; k++) xv[k] = x[(size_t)node * NDIM + k];

    float o[4] = {0.f, 0.f, 0.f, 0.f};
    #pragma unroll
    for (int k = 0; k < NDIM; k++) {
        const float4 w = *(const float4*)&Ws[k][lane * 4];
        o[0] = fmaf(xv[k], w.x, o[0]);
        o[1] = fmaf(xv[k], w.y, o[1]);
        o[2] = fmaf(xv[k], w.z, o[2]);
        o[3] = fmaf(xv[k], w.w, o[3]);
    }
    const float d = g_dinv[node];
    union { __nv_bfloat162 h2[2]; uint2 u; } cvt;
    cvt.h2[0] = __floats2bfloat162_rn(o[0] * d, o[1] * d);
    cvt.h2[1] = __floats2bfloat162_rn(o[2] * d, o[3] * d);
    *(uint2*)&out[(size_t)node * 64 + lane * 4] = cvt.u;
}

// ---------------- 2b) layer 1: pure gather + bias + relu (no GEMM) ----------
// in = XW' (pre-scaled by dinv_j). out_i = dinv_i * relu(dinv_i*sum + b1).
// 128 threads, 8 lanes/node -> 16 nodes/block, grid 2048. No shared, no syncs.
__global__ __launch_bounds__(128)
void gather_relu_kernel(const __nv_bfloat16* __restrict__ in,
                        const float* __restrict__ bias,
                        __nv_bfloat16* __restrict__ out) {
    const int tid   = threadIdx.x;
    const int grp   = tid >> 3;      // 0..15
    const int lane  = tid & 7;       // 0..7
    const int node  = blockIdx.x * 16 + grp;
    const int bbase = node & ~(NN - 1);

    float acc[8];
    gather_node(in, &g_nbr[(size_t)node * MAXD], g_cnt[node], bbase, lane, acc);

    const float di = g_dinv[node];
    const float4 b0 = *(const float4*)&bias[lane * 8];
    const float4 b1 = *(const float4*)&bias[lane * 8 + 4];
    float o[8];
    o[0] = fmaxf(fmaf(di, acc[0], b0.x), 0.f) * di;
    o[1] = fmaxf(fmaf(di, acc[1], b0.y), 0.f) * di;
    o[2] = fmaxf(fmaf(di, acc[2], b0.z), 0.f) * di;
    o[3] = fmaxf(fmaf(di, acc[3], b0.w), 0.f) * di;
    o[4] = fmaxf(fmaf(di, acc[4], b1.x), 0.f) * di;
    o[5] = fmaxf(fmaf(di, acc[5], b1.y), 0.f) * di;
    o[6] = fmaxf(fmaf(di, acc[6], b1.z), 0.f) * di;
    o[7] = fmaxf(fmaf(di, acc[7], b1.w), 0.f) * di;
    st_bf16x8(&out[(size_t)node * 64 + lane * 8], o);
}

// ---------------- 2c) layers 2/3: gather + GEMM + bias + relu ---------------
// 128 threads, 32 nodes/block. Gather: 8 lanes/node, 2 sequential nodes/group.
// SCALE_OUT: store dinv_i * relu (layer 2). POOL: only emit block column sums (layer 3).
template <bool SCALE_OUT, bool POOL>
__global__ __launch_bounds__(128)
void gcn_layer_kernel(const __nv_bfloat16* __restrict__ in,
                      const float* __restrict__ W,
                      const float* __restrict__ bias,
                      __nv_bfloat16* __restrict__ out) {
    __shared__ float Ag[NODES_PER_BLK][68];
    __shared__ float Ws[64][64];
    __shared__ float bs[64];

    const int tid       = threadIdx.x;
    const int blockBase = blockIdx.x * NODES_PER_BLK;
    const int bbase     = blockBase & ~(NN - 1);

    #pragma unroll
    for (int i = tid; i < 64 * 16; i += 128)
        ((float4*)Ws)[i] = ((const float4*)W)[i];
    if (tid < 64) bs[tid] = bias[tid];

    // ---- Phase A: gather ----
    {
        const int grp  = tid >> 3;   // 0..15
        const int lane = tid & 7;    // 0..7
        #pragma unroll
        for (int s = 0; s < 2; s++) {
            const int n    = grp * 2 + s;
            const int node = blockBase + n;
            float acc[8];
            gather_node(in, &g_nbr[(size_t)node * MAXD], g_cnt[node], bbase, lane, acc);
            const float di = g_dinv[node];
            float4 lo = make_float4(acc[0] * di, acc[1] * di, acc[2] * di, acc[3] * di);
            float4 hi = make_float4(acc[4] * di, acc[5] * di, acc[6] * di, acc[7] * di);
            *(float4*)&Ag[n][lane * 8]     = lo;
            *(float4*)&Ag[n][lane * 8 + 4] = hi;
        }
    }
    __syncthreads();

    // ---- Phase B: [32 x 64] @ [64 x 64], 4x4 microtiles ----
    {
        const int tx = tid & 15;
        const int ty = tid >> 4;
        float c[4][4];
        #pragma unroll
        for (int i = 0; i < 4; i++)
            #pragma unroll
            for (int j = 0; j < 4; j++) c[i][j] = 0.0f;

        #pragma unroll
        for (int kk = 0; kk < 64; kk += 4) {
            float4 a[4], b[4];
            #pragma unroll
            for (int i = 0; i < 4; i++) a[i] = *(const float4*)&Ag[ty * 4 + i][kk];
            #pragma unroll
            for (int q = 0; q < 4; q++) b[q] = *(const float4*)&Ws[kk + q][tx * 4];
            #pragma unroll
            for (int i = 0; i < 4; i++) {
                const float ai[4] = {a[i].x, a[i].y, a[i].z, a[i].w};
                #pragma unroll
                for (int q = 0; q < 4; q++) {
                    c[i][0] = fmaf(ai[q], b[q].x, c[i][0]);
                    c[i][1] = fmaf(ai[q], b[q].y, c[i][1]);
                    c[i][2] = fmaf(ai[q], b[q].z, c[i][2]);
                    c[i][3] = fmaf(ai[q], b[q].w, c[i][3]);
                }
            }
        }

        float colsum[4] = {0.f, 0.f, 0.f, 0.f};
        #pragma unroll
        for (int i = 0; i < 4; i++) {
            const int row = blockBase + ty * 4 + i;
            float4 o;
            o.x = fmaxf(c[i][0] + bs[tx * 4 + 0], 0.0f);
            o.y = fmaxf(c[i][1] + bs[tx * 4 + 1], 0.0f);
            o.z = fmaxf(c[i][2] + bs[tx * 4 + 2], 0.0f);
            o.w = fmaxf(c[i][3] + bs[tx * 4 + 3], 0.0f);
            if (POOL) {
                colsum[0] += o.x; colsum[1] += o.y;
                colsum[2] += o.z; colsum[3] += o.w;
            } else {
                const float dscale = SCALE_OUT ? g_dinv[row] : 1.0f;
                union { __nv_bfloat162 h2[2]; uint2 u; } cvt;
                cvt.h2[0] = __floats2bfloat162_rn(o.x * dscale, o.y * dscale);
                cvt.h2[1] = __floats2bfloat162_rn(o.z * dscale, o.w * dscale);
                *(uint2*)&out[(size_t)row * 64 + tx * 4] = cvt.u;
            }
        }

        if (POOL) {
            __syncthreads();               // done reading Ag; reuse it
            #pragma unroll
            for (int q = 0; q < 4; q++) Ag[ty][tx * 4 + q] = colsum[q];
            __syncthreads();
            if (tid < 64) {
                float s = 0.0f;
                #pragma unroll
                for (int r = 0; r < 8; r++) s += Ag[r][tid];
                g_pool[blockIdx.x * HID + tid] = s;
            }
        }
    }
}

// ---------------- 3) head: combine partials + MLP ----------------
__global__ void head_kernel(const float* __restrict__ Wf1,
                            const float* __restrict__ bf1,
                            const float* __restrict__ Wf2,
                            const float* __restrict__ bf2,
                            float* __restrict__ out) {
    const int b = blockIdx.x, tid = threadIdx.x;
    const int chunks = NN / NODES_PER_BLK;   // 32 partials per batch
    __shared__ float pooled[64];
    __shared__ float red[128];

    if (tid < 64) {
        float s = 0.0f;
        #pragma unroll
        for (int c = 0; c < chunks; c++) s += g_pool[(b * chunks + c) * HID + tid];
        pooled[tid] = s * (1.0f / (float)NN);
    }
    __syncthreads();

    float a = bf1[tid];
    #pragma unroll
    for (int kk = 0; kk < 64; kk++) a = fmaf(pooled[kk], Wf1[kk * HEAD + tid], a);
    red[tid] = fmaxf(a, 0.0f) * Wf2[tid];
    __syncthreads();
    for (int off = 64; off > 0; off >>= 1) {
        if (tid < off) red[tid] += red[tid + off];
        __syncthreads();
    }
    if (tid == 0) out[b] = red[0] + bf2[0];
}

// ---------------- launch ----------------
extern "C" void kernel_launch(void* const* d_in, const int* in_sizes, int n_in,
                              void* d_out, int out_size) {
    const float* x   = (const float*)d_in[0];
    const float* adj = (const float*)d_in[1];
    const float* W1  = (const float*)d_in[2];
    const float* b1  = (const float*)d_in[3];
    const float* W2  = (const float*)d_in[4];
    const float* b2  = (const float*)d_in[5];
    const float* W3  = (const float*)d_in[6];
    const float* b3  = (const float*)d_in[7];
    const float* Wf1 = (const float*)d_in[8];
    const float* bf1 = (const float*)d_in[9];
    const float* Wf2 = (const float*)d_in[10];
    const float* bf2 = (const float*)d_in[11];
    float* out = (float*)d_out;

    __nv_bfloat16 *xw, *h1, *h2;
    cudaGetSymbolAddress((void**)&xw, g_xw);
    cudaGetSymbolAddress((void**)&h1, g_h1);
    cudaGetSymbolAddress((void**)&h2, g_h2);

    build_edges_kernel<<<TOTAL_NODES / 8, 256>>>(adj);
    xw_kernel<<<TOTAL_NODES / 8, 128>>>(x, W1, xw);
    gather_relu_kernel<<<TOTAL_NODES / 16, 128>>>(xw, b1, h1);
    gcn_layer_kernel<true,  false><<<NBLK, 128>>>(h1, W2, b2, h2);
    gcn_layer_kernel<false, true ><<<NBLK, 128>>>(h2, W3, b3, h1);
    head_kernel<<<BATCH, 128>>>(Wf1, bf1, Wf2, bf2, out);
}